// round 1
// baseline (speedup 1.0000x reference)
#include <cuda_runtime.h>

#define TSEQ 512
#define INF  14
#define HID  8

__device__ __forceinline__ float sigf(float x){
    // 1/(1+exp(-x)); exp overflow -> inf -> rcp -> 0 (correct limit), no clamp needed
    return __fdividef(1.0f, 1.0f + __expf(-x));
}
__device__ __forceinline__ float tanh_f(float x){
    // 2/(1+exp(-2x)) - 1; safe at both infinities, no NaN
    return __fdividef(2.0f, 1.0f + __expf(-2.0f * x)) - 1.0f;
}

__global__ __launch_bounds__(128, 1) void lstm_forex_kernel(
    const float* __restrict__ x,
    const float* __restrict__ Wih1, const float* __restrict__ Whh1,
    const float* __restrict__ bih1, const float* __restrict__ bhh1,
    const float* __restrict__ Wih2, const float* __restrict__ Whh2,
    const float* __restrict__ bih2, const float* __restrict__ bhh2,
    const float* __restrict__ bn_gamma, const float* __restrict__ bn_beta,
    const float* __restrict__ bn_mean, const float* __restrict__ bn_var,
    const float* __restrict__ w1, const float* __restrict__ b1,
    const float* __restrict__ w2, const float* __restrict__ b2,
    float* __restrict__ out, int Bn)
{
    const int tid  = blockIdx.x * blockDim.x + threadIdx.x;
    const int lane = tid & 31;
    const int warp = tid >> 5;
    const int j    = lane & 7;          // h-index this lane owns
    const int base = lane & 24;         // base lane of this element's 8-lane group
    const int e    = warp * 4 + (lane >> 3);
    const bool valid = (e < Bn);
    const int ec = valid ? e : (Bn > 0 ? Bn - 1 : 0);
    const unsigned FULL = 0xffffffffu;

    // ---- load per-lane weight rows (gates i,f,g,o = rows j, j+8, j+16, j+24) ----
    float wx[4][14], wh1r[4][8], wi2r[4][8], wh2r[4][8], b1s[4], b2s[4];
#pragma unroll
    for (int g = 0; g < 4; g++){
        const int row = g * 8 + j;
#pragma unroll
        for (int k = 0; k < 14; k++) wx[g][k] = Wih1[row * 14 + k];
#pragma unroll
        for (int k = 0; k < 8; k++){
            wh1r[g][k] = Whh1[row * 8 + k];
            wi2r[g][k] = Wih2[row * 8 + k];
            wh2r[g][k] = Whh2[row * 8 + k];
        }
        b1s[g] = bih1[row] + bhh1[row];
        b2s[g] = bih2[row] + bhh2[row];
    }

    // x[e, t, :] : 14 floats, 8-byte aligned (14 even) -> 7x float2
    const float2* px = reinterpret_cast<const float2*>(x) + (size_t)ec * (TSEQ * INF / 2);
    float2 xb[7];
#pragma unroll
    for (int k = 0; k < 7; k++) xb[k] = px[k];
    px += 7;

    float h1 = 0.f, c1 = 0.f, h2 = 0.f, c2 = 0.f;

#pragma unroll 1
    for (int t = 0; t < TSEQ; t++){
        // ---------------- layer 1: input projection (consume xb) ----------------
        float a0 = b1s[0], a1 = b1s[1], a2 = b1s[2], a3 = b1s[3];
#pragma unroll
        for (int k = 0; k < 7; k++){
            const float xa = xb[k].x, xc = xb[k].y;
            a0 = fmaf(wx[0][2*k], xa, a0); a0 = fmaf(wx[0][2*k+1], xc, a0);
            a1 = fmaf(wx[1][2*k], xa, a1); a1 = fmaf(wx[1][2*k+1], xc, a1);
            a2 = fmaf(wx[2][2*k], xa, a2); a2 = fmaf(wx[2][2*k+1], xc, a2);
            a3 = fmaf(wx[3][2*k], xa, a3); a3 = fmaf(wx[3][2*k+1], xc, a3);
        }
        // prefetch next timestep's x (one iteration of latency cover)
        if (t + 1 < TSEQ){
#pragma unroll
            for (int k = 0; k < 7; k++) xb[k] = px[k];
            px += 7;
        }
        // ---------------- layer 1: recurrent part ----------------
#pragma unroll
        for (int k = 0; k < 8; k++){
            const float hk = __shfl_sync(FULL, h1, base + k);
            a0 = fmaf(wh1r[0][k], hk, a0);
            a1 = fmaf(wh1r[1][k], hk, a1);
            a2 = fmaf(wh1r[2][k], hk, a2);
            a3 = fmaf(wh1r[3][k], hk, a3);
        }
        {
            const float ai = sigf(a0), af = sigf(a1), ag = tanh_f(a2), ao = sigf(a3);
            c1 = fmaf(af, c1, ai * ag);
            h1 = ao * tanh_f(c1);
        }
        // ---------------- layer 2 ----------------
        a0 = b2s[0]; a1 = b2s[1]; a2 = b2s[2]; a3 = b2s[3];
#pragma unroll
        for (int k = 0; k < 8; k++){
            const float h1k = __shfl_sync(FULL, h1, base + k);
            const float h2k = __shfl_sync(FULL, h2, base + k);
            a0 = fmaf(wi2r[0][k], h1k, a0); a0 = fmaf(wh2r[0][k], h2k, a0);
            a1 = fmaf(wi2r[1][k], h1k, a1); a1 = fmaf(wh2r[1][k], h2k, a1);
            a2 = fmaf(wi2r[2][k], h1k, a2); a2 = fmaf(wh2r[2][k], h2k, a2);
            a3 = fmaf(wi2r[3][k], h1k, a3); a3 = fmaf(wh2r[3][k], h2k, a3);
        }
        {
            const float ai = sigf(a0), af = sigf(a1), ag = tanh_f(a2), ao = sigf(a3);
            c2 = fmaf(af, c2, ai * ag);
            h2 = ao * tanh_f(c2);
        }
    }

    // ---------------- epilogue: BatchNorm (eval) + MLP head ----------------
    const float scale = bn_gamma[j] * rsqrtf(bn_var[j] + 1e-5f);
    const float nrm   = fmaf(h2 - bn_mean[j], scale, bn_beta[j]);

    float p0 = w1[0 * 8 + j] * nrm;
    float p1 = w1[1 * 8 + j] * nrm;
    float p2 = w1[2 * 8 + j] * nrm;
    float p3 = w1[3 * 8 + j] * nrm;
#pragma unroll
    for (int off = 4; off > 0; off >>= 1){
        p0 += __shfl_xor_sync(FULL, p0, off);
        p1 += __shfl_xor_sync(FULL, p1, off);
        p2 += __shfl_xor_sync(FULL, p2, off);
        p3 += __shfl_xor_sync(FULL, p3, off);
    }
    if (valid && j == 0){
        float o = b2[0];
        o = fmaf(w2[0], fmaxf(p0 + b1[0], 0.f), o);
        o = fmaf(w2[1], fmaxf(p1 + b1[1], 0.f), o);
        o = fmaf(w2[2], fmaxf(p2 + b1[2], 0.f), o);
        o = fmaf(w2[3], fmaxf(p3 + b1[3], 0.f), o);
        out[e] = o;
    }
}

extern "C" void kernel_launch(void* const* d_in, const int* in_sizes, int n_in,
                              void* d_out, int out_size)
{
    const float* x        = (const float*)d_in[0];
    const float* Wih1     = (const float*)d_in[1];
    const float* Whh1     = (const float*)d_in[2];
    const float* bih1     = (const float*)d_in[3];
    const float* bhh1     = (const float*)d_in[4];
    const float* Wih2     = (const float*)d_in[5];
    const float* Whh2     = (const float*)d_in[6];
    const float* bih2     = (const float*)d_in[7];
    const float* bhh2     = (const float*)d_in[8];
    const float* bn_gamma = (const float*)d_in[9];
    const float* bn_beta  = (const float*)d_in[10];
    const float* bn_mean  = (const float*)d_in[11];
    const float* bn_var   = (const float*)d_in[12];
    const float* w1       = (const float*)d_in[13];
    const float* b1       = (const float*)d_in[14];
    const float* w2       = (const float*)d_in[15];
    const float* b2       = (const float*)d_in[16];

    const int Bn = in_sizes[0] / (TSEQ * INF);
    const int warps = (Bn + 3) / 4;          // 4 batch elements per warp
    const int threads = warps * 32;
    const int block = 128;
    const int grid = (threads + block - 1) / block;

    lstm_forex_kernel<<<grid, block>>>(x, Wih1, Whh1, bih1, bhh1,
                                       Wih2, Whh2, bih2, bhh2,
                                       bn_gamma, bn_beta, bn_mean, bn_var,
                                       w1, b1, w2, b2,
                                       (float*)d_out, Bn);
}